// round 2
// baseline (speedup 1.0000x reference)
#include <cuda_runtime.h>
#include <math.h>

#define LL1 1024
#define CC 384
#define HH 12
#define PP 128

#define SCALAR_W 0.14433756729740643f
#define POINT_WC 0.13608276348795434f
#define PAIR_W   0.5773502691896258f

#define PROJ 1152
#define FEAT 2112

// ------------- static scratch (no runtime allocation) -------------
__device__ float g_proj[LL1 * PROJ];
__device__ float g_q   [LL1 * 192];       // [i][h*16+s] (scaled)
__device__ float g_kT  [HH * 16 * LL1];   // [(h*16+s)][j]
__device__ float g_vT  [HH * 16 * LL1];   // [(h*16+c)][j]
__device__ float g_qp  [LL1 * 144];       // [i][h*12 + n*3+r] global frame
__device__ float g_kpT [HH * 12 * LL1];   // [(h*12+nr)][j]
__device__ float g_vpT [HH * 24 * LL1];   // [(h*24+nr)][j]
__device__ float g_sqq [HH * LL1];
__device__ float g_sqk [HH * LL1];
__device__ float g_Z   [(size_t)HH * LL1 * LL1];   // pair logits -> attn (in place)
__device__ float g_feat[(size_t)LL1 * FEAT];

// ------------- K1: projection GEMM X[1024x384] @ W[384x1152] -------------
__device__ __forceinline__ float wload(int r, int gc, const float* Wq,
    const float* Wkv, const float* Wqp, const float* Wkvp) {
  if (gc < 192) return Wq[r * 192 + gc];
  if (gc < 576) return Wkv[r * 384 + (gc - 192)];
  if (gc < 720) return Wqp[r * 144 + (gc - 576)];
  return Wkvp[r * 432 + (gc - 720)];
}

__global__ void k_projgemm(const float* __restrict__ x1d, const float* __restrict__ Wq,
                           const float* __restrict__ Wkv, const float* __restrict__ Wqp,
                           const float* __restrict__ Wkvp) {
  __shared__ float s_x[16][68];
  __shared__ float s_w[16][128];
  int tid = threadIdx.x;
  int tx = tid & 15, ty = tid >> 4;
  int i0 = blockIdx.x * 64, c0 = blockIdx.y * 128;
  float acc[4][8] = {};
  for (int k0 = 0; k0 < CC; k0 += 16) {
    __syncthreads();
    for (int idx = tid; idx < 1024; idx += 256) {
      int il = idx >> 4, kk = idx & 15;
      s_x[kk][il] = x1d[(i0 + il) * CC + k0 + kk];
    }
    for (int idx = tid; idx < 2048; idx += 256) {
      int kk = idx >> 7, cl = idx & 127;
      s_w[kk][cl] = wload(k0 + kk, c0 + cl, Wq, Wkv, Wqp, Wkvp);
    }
    __syncthreads();
#pragma unroll
    for (int kk = 0; kk < 16; kk++) {
      float xv[4], wv[8];
#pragma unroll
      for (int r = 0; r < 4; r++) xv[r] = s_x[kk][ty * 4 + r];
#pragma unroll
      for (int c = 0; c < 8; c++) wv[c] = s_w[kk][tx * 8 + c];
#pragma unroll
      for (int r = 0; r < 4; r++)
#pragma unroll
        for (int c = 0; c < 8; c++) acc[r][c] += xv[r] * wv[c];
    }
  }
#pragma unroll
  for (int r = 0; r < 4; r++)
#pragma unroll
    for (int c = 0; c < 8; c++)
      g_proj[(size_t)(i0 + ty * 4 + r) * PROJ + c0 + tx * 8 + c] = acc[r][c];
}

// ------------- K2: bias/split/rigid/norms per residue -------------
__global__ void k_post(const float* __restrict__ rot, const float* __restrict__ trans,
                       const float* __restrict__ bq, const float* __restrict__ bkv,
                       const float* __restrict__ bqp, const float* __restrict__ bkvp) {
  int i = blockIdx.x, tid = threadIdx.x;
  __shared__ float s_R[9], s_t[3], s_pt[96][3];
  if (tid < 9) s_R[tid] = rot[i * 9 + tid];
  else if (tid < 12) s_t[tid - 9] = trans[i * 3 + tid - 9];
  __syncthreads();
  const float* pr = &g_proj[(size_t)i * PROJ];
  for (int idx = tid; idx < 576; idx += 256) {
    if (idx < 192) {
      g_q[(size_t)i * 192 + idx] = (pr[idx] + bq[idx]) * SCALAR_W;
    } else {
      int m = idx - 192, hh = m >> 5, t = m & 31;
      float v = pr[idx] + bkv[m];
      if (t < 16) g_kT[(hh * 16 + t) * LL1 + i] = v;
      else        g_vT[(hh * 16 + t - 16) * LL1 + i] = v;
    }
  }
  for (int m = tid; m < 192; m += 256) {
    float p0, p1, p2;
    if (m < 48) {
      p0 = pr[576 + m] + bqp[m];
      p1 = pr[624 + m] + bqp[48 + m];
      p2 = pr[672 + m] + bqp[96 + m];
    } else {
      int mm = m - 48;
      p0 = pr[720 + mm] + bkvp[mm];
      p1 = pr[864 + mm] + bkvp[144 + mm];
      p2 = pr[1008 + mm] + bkvp[288 + mm];
    }
    float gx = s_R[0] * p0 + s_R[1] * p1 + s_R[2] * p2 + s_t[0];
    float gy = s_R[3] * p0 + s_R[4] * p1 + s_R[5] * p2 + s_t[1];
    float gz = s_R[6] * p0 + s_R[7] * p1 + s_R[8] * p2 + s_t[2];
    if (m < 48) {
      int hh = m >> 2, n = m & 3;
      size_t b = (size_t)i * 144 + hh * 12 + n * 3;
      g_qp[b] = gx; g_qp[b + 1] = gy; g_qp[b + 2] = gz;
      s_pt[m][0] = gx; s_pt[m][1] = gy; s_pt[m][2] = gz;
    } else {
      int mm = m - 48, hh = mm / 12, t = mm % 12;
      if (t < 4) {
        int b = (hh * 12 + t * 3) * LL1 + i;
        g_kpT[b] = gx; g_kpT[b + LL1] = gy; g_kpT[b + 2 * LL1] = gz;
        int sp = 48 + hh * 4 + t;
        s_pt[sp][0] = gx; s_pt[sp][1] = gy; s_pt[sp][2] = gz;
      } else {
        int b = (hh * 24 + (t - 4) * 3) * LL1 + i;
        g_vpT[b] = gx; g_vpT[b + LL1] = gy; g_vpT[b + 2 * LL1] = gz;
      }
    }
  }
  __syncthreads();
  if (tid < 24) {
    int hh = tid % 12; bool isq = tid < 12;
    float s = 0.f;
#pragma unroll
    for (int n = 0; n < 4; n++) {
      const float* p = s_pt[(isq ? 0 : 48) + hh * 4 + n];
      s += p[0] * p[0] + p[1] * p[1] + p[2] * p[2];
    }
    if (isq) g_sqq[hh * LL1 + i] = s;
    else     g_sqk[hh * LL1 + i] = s;
  }
}

// ------------- K3: pair-bias GEMM, block = one i (1024 j x 128 c -> 12 h) ---
__global__ void k_pair(const float* __restrict__ x2d, const float* __restrict__ Wp,
                       const float* __restrict__ bp) {
  __shared__ float s_A[8][1024];
  __shared__ float s_W[1536];
  __shared__ float s_b[12];
  int i = blockIdx.x, tid = threadIdx.x;
  for (int t = tid; t < 1536; t += 256) s_W[t] = Wp[t];
  if (tid < 12) s_b[tid] = bp[tid];
  float acc[4][12] = {};
  const float* xrow = x2d + (size_t)i * LL1 * PP;
  for (int k0 = 0; k0 < 128; k0 += 8) {
    __syncthreads();
#pragma unroll
    for (int p = 0; p < 8; p++) {
      int idx = p * 256 + tid;
      int r = idx >> 1, qq = idx & 1;
      float4 v = *(const float4*)(xrow + (size_t)r * 128 + k0 + qq * 4);
      s_A[qq * 4 + 0][r] = v.x; s_A[qq * 4 + 1][r] = v.y;
      s_A[qq * 4 + 2][r] = v.z; s_A[qq * 4 + 3][r] = v.w;
    }
    __syncthreads();
#pragma unroll
    for (int kk = 0; kk < 8; kk++) {
      float av[4];
#pragma unroll
      for (int q = 0; q < 4; q++) av[q] = s_A[kk][q * 256 + tid];
#pragma unroll
      for (int hh = 0; hh < 12; hh++) {
        float wv = s_W[(k0 + kk) * 12 + hh];
#pragma unroll
        for (int q = 0; q < 4; q++) acc[q][hh] += av[q] * wv;
      }
    }
  }
  for (int hh = 0; hh < 12; hh++) {
    float bb = s_b[hh];
#pragma unroll
    for (int q = 0; q < 4; q++)
      g_Z[(size_t)(hh * LL1 + i) * LL1 + q * 256 + tid] = PAIR_W * (acc[q][hh] + bb);
  }
}

// ------------- K4: logits + softmax, 8 i-rows per block, attn in place -----
__global__ void k_logits(const float* __restrict__ tpw) {
  int i0 = blockIdx.x * 8, h = blockIdx.y;
  int tid = threadIdx.x;
  __shared__ float s_l[8][1024];
  __shared__ float s_q[8][16], s_qp[8][12], s_sqq[8];
  __shared__ float s_red[8];
  __shared__ float s_bc, s_pw;
  if (tid < 128) s_q[tid >> 4][tid & 15] = g_q[(size_t)(i0 + (tid >> 4)) * 192 + h * 16 + (tid & 15)];
  else if (tid < 224) { int m = tid - 128; s_qp[m / 12][m % 12] = g_qp[(size_t)(i0 + m / 12) * 144 + h * 12 + m % 12]; }
  else if (tid < 232) s_sqq[tid - 224] = g_sqq[h * LL1 + i0 + tid - 224];
  else if (tid == 232) {
    float x = tpw[h];
    s_pw = -0.5f * POINT_WC * (fmaxf(x, 0.f) + log1pf(expf(-fabsf(x))));
  }
  __syncthreads();
  float pw = s_pw;
  for (int j = tid; j < 1024; j += 256) {
    float kv[16], kp[12];
#pragma unroll
    for (int s = 0; s < 16; s++) kv[s] = g_kT[(h * 16 + s) * LL1 + j];
#pragma unroll
    for (int r = 0; r < 12; r++) kp[r] = g_kpT[(h * 12 + r) * LL1 + j];
    float sqk = g_sqk[h * LL1 + j];
#pragma unroll
    for (int ii = 0; ii < 8; ii++) {
      float d = 0.f, pq = 0.f;
#pragma unroll
      for (int s = 0; s < 16; s++) d += s_q[ii][s] * kv[s];
#pragma unroll
      for (int r = 0; r < 12; r++) pq += s_qp[ii][r] * kp[r];
      float pair = g_Z[(size_t)(h * LL1 + i0 + ii) * LL1 + j];
      s_l[ii][j] = d + pw * (s_sqq[ii] + sqk - 2.f * pq) + pair;
    }
  }
  __syncthreads();
  int lane = tid & 31, w = tid >> 5;
  for (int ii = 0; ii < 8; ii++) {
    float m = -3.4e38f;
    for (int j = tid; j < 1024; j += 256) m = fmaxf(m, s_l[ii][j]);
    for (int o = 16; o; o >>= 1) m = fmaxf(m, __shfl_xor_sync(~0u, m, o));
    if (lane == 0) s_red[w] = m;
    __syncthreads();
    if (tid == 0) { float mm = s_red[0]; for (int q = 1; q < 8; q++) mm = fmaxf(mm, s_red[q]); s_bc = mm; }
    __syncthreads();
    m = s_bc;
    float sum = 0.f;
    for (int j = tid; j < 1024; j += 256) { float e = __expf(s_l[ii][j] - m); s_l[ii][j] = e; sum += e; }
    for (int o = 16; o; o >>= 1) sum += __shfl_xor_sync(~0u, sum, o);
    if (lane == 0) s_red[w] = sum;
    __syncthreads();
    if (tid == 0) { float ss = 0.f; for (int q = 0; q < 8; q++) ss += s_red[q]; s_bc = 1.f / ss; }
    __syncthreads();
    float inv = s_bc;
    float* zr = &g_Z[(size_t)(h * LL1 + i0 + ii) * LL1];
    for (int j = tid; j < 1024; j += 256) zr[j] = s_l[ii][j] * inv;
    __syncthreads();
  }
}

// ------------- K5: attn @ {v_s, vp} + inverse rigid + f_n -------------
__global__ void k_attnout(const float* __restrict__ rot, const float* __restrict__ trans) {
  int i0 = blockIdx.x * 8, h = blockIdx.y;
  int tid = threadIdx.x, lane = tid & 31, w = tid >> 5;
  __shared__ float s_out[40][8];
  float acc[5][8];
#pragma unroll
  for (int c = 0; c < 5; c++)
#pragma unroll
    for (int ii = 0; ii < 8; ii++) acc[c][ii] = 0.f;
  const float* vptr[5];
#pragma unroll
  for (int c = 0; c < 5; c++) {
    int ch = w * 5 + c;
    vptr[c] = (ch < 16) ? &g_vT[(h * 16 + ch) * LL1] : &g_vpT[(h * 24 + ch - 16) * LL1];
  }
  for (int j = lane; j < 1024; j += 32) {
    float a[8];
#pragma unroll
    for (int ii = 0; ii < 8; ii++) a[ii] = g_Z[(size_t)(h * LL1 + i0 + ii) * LL1 + j];
#pragma unroll
    for (int c = 0; c < 5; c++) {
      float v = vptr[c][j];
#pragma unroll
      for (int ii = 0; ii < 8; ii++) acc[c][ii] += a[ii] * v;
    }
  }
#pragma unroll
  for (int c = 0; c < 5; c++)
#pragma unroll
    for (int ii = 0; ii < 8; ii++) {
      float s = acc[c][ii];
      for (int o = 16; o; o >>= 1) s += __shfl_xor_sync(~0u, s, o);
      if (lane == 0) s_out[w * 5 + c][ii] = s;
    }
  __syncthreads();
  if (tid < 128) {
    int ii = tid >> 4, c = tid & 15;
    g_feat[(size_t)(i0 + ii) * FEAT + h * 16 + c] = s_out[c][ii];
  } else if (tid < 192) {
    int p = tid - 128, ii = p >> 3, n = p & 7;
    int gi = i0 + ii;
    float R[9], t[3];
#pragma unroll
    for (int q = 0; q < 9; q++) R[q] = rot[gi * 9 + q];
#pragma unroll
    for (int q = 0; q < 3; q++) t[q] = trans[gi * 3 + q];
    float d0 = s_out[16 + n * 3 + 0][ii] - t[0];
    float d1 = s_out[16 + n * 3 + 1][ii] - t[1];
    float d2 = s_out[16 + n * 3 + 2][ii] - t[2];
    float lx = R[0] * d0 + R[3] * d1 + R[6] * d2;
    float ly = R[1] * d0 + R[4] * d1 + R[7] * d2;
    float lz = R[2] * d0 + R[5] * d1 + R[8] * d2;
    size_t base = (size_t)gi * FEAT;
    g_feat[base + 192 + 0 * 96 + h * 8 + n] = lx;
    g_feat[base + 192 + 1 * 96 + h * 8 + n] = ly;
    g_feat[base + 192 + 2 * 96 + h * 8 + n] = lz;
    g_feat[base + 480 + h * 8 + n] = sqrtf(lx * lx + ly * ly + lz * lz + 1e-8f);
  }
}

// ------------- K6: r_2d = attn @ inputs_2d, block = one i -------------
__global__ void k_r2d(const float* __restrict__ x2d) {
  int i = blockIdx.x, tid = threadIdx.x;
  int c = tid & 127, g = tid >> 7;  // g in 0..2, 4 heads each
  __shared__ float s_at[256 * 12];
  float acc[4] = {0.f, 0.f, 0.f, 0.f};
  for (int j0 = 0; j0 < 1024; j0 += 256) {
    __syncthreads();
    for (int idx = tid; idx < 3072; idx += 384) {
      int hh = idx >> 8, jj = idx & 255;
      s_at[jj * 12 + hh] = g_Z[(size_t)(hh * LL1 + i) * LL1 + j0 + jj];
    }
    __syncthreads();
    const float* xr = x2d + ((size_t)i * LL1 + j0) * PP + c;
    for (int jj = 0; jj < 256; jj++) {
      float xv = xr[(size_t)jj * PP];
      float4 av = *(const float4*)&s_at[jj * 12 + g * 4];
      acc[0] += av.x * xv; acc[1] += av.y * xv;
      acc[2] += av.z * xv; acc[3] += av.w * xv;
    }
  }
  size_t base = (size_t)i * FEAT + 576 + c;
#pragma unroll
  for (int q = 0; q < 4; q++) g_feat[base + (size_t)(g * 4 + q) * PP] = acc[q];
}

// ------------- K7: output GEMM feat[1024x2112] @ Wout[2112x384] -------------
__global__ void k_outgemm(const float* __restrict__ Wout, const float* __restrict__ bout,
                          float* __restrict__ out) {
  __shared__ float s_f[16][68];
  __shared__ float s_w[16][128];
  int tid = threadIdx.x;
  int tx = tid & 15, ty = tid >> 4;
  int i0 = blockIdx.x * 64, c0 = blockIdx.y * 128;
  float acc[4][8] = {};
  for (int k0 = 0; k0 < FEAT; k0 += 16) {
    __syncthreads();
    for (int idx = tid; idx < 1024; idx += 256) {
      int il = idx >> 4, kk = idx & 15;
      s_f[kk][il] = g_feat[(size_t)(i0 + il) * FEAT + k0 + kk];
    }
    for (int idx = tid; idx < 2048; idx += 256) {
      int kk = idx >> 7, cl = idx & 127;
      s_w[kk][cl] = Wout[(size_t)(k0 + kk) * 384 + c0 + cl];
    }
    __syncthreads();
#pragma unroll
    for (int kk = 0; kk < 16; kk++) {
      float xv[4], wv[8];
#pragma unroll
      for (int r = 0; r < 4; r++) xv[r] = s_f[kk][ty * 4 + r];
#pragma unroll
      for (int cc = 0; cc < 8; cc++) wv[cc] = s_w[kk][tx * 8 + cc];
#pragma unroll
      for (int r = 0; r < 4; r++)
#pragma unroll
        for (int cc = 0; cc < 8; cc++) acc[r][cc] += xv[r] * wv[cc];
    }
  }
#pragma unroll
  for (int r = 0; r < 4; r++) {
    int ii = i0 + ty * 4 + r;
#pragma unroll
    for (int cc = 0; cc < 8; cc++) {
      int ccol = c0 + tx * 8 + cc;
      out[(size_t)ii * 384 + ccol] = acc[r][cc] + bout[ccol];
    }
  }
}

// ------------- launch -------------
extern "C" void kernel_launch(void* const* d_in, const int* in_sizes, int n_in,
                              void* d_out, int out_size) {
  (void)in_sizes; (void)n_in; (void)out_size;
  const float* x1d   = (const float*)d_in[0];
  const float* x2d   = (const float*)d_in[1];
  const float* rot   = (const float*)d_in[2];
  const float* trans = (const float*)d_in[3];
  // d_in[4] = mask (all true by construction) — unused
  const float* Wq    = (const float*)d_in[5];
  const float* bq    = (const float*)d_in[6];
  const float* Wkv   = (const float*)d_in[7];
  const float* bkv   = (const float*)d_in[8];
  const float* Wqp   = (const float*)d_in[9];
  const float* bqp   = (const float*)d_in[10];
  const float* Wkvp  = (const float*)d_in[11];
  const float* bkvp  = (const float*)d_in[12];
  const float* Wpair = (const float*)d_in[13];
  const float* bpair = (const float*)d_in[14];
  const float* tpw   = (const float*)d_in[15];
  const float* Wout  = (const float*)d_in[16];
  const float* bout  = (const float*)d_in[17];
  float* out = (float*)d_out;

  k_projgemm<<<dim3(16, 9), 256>>>(x1d, Wq, Wkv, Wqp, Wkvp);
  k_post<<<1024, 256>>>(rot, trans, bq, bkv, bqp, bkvp);
  k_pair<<<1024, 256>>>(x2d, Wpair, bpair);
  k_logits<<<dim3(128, 12), 256>>>(tpw);
  k_attnout<<<dim3(128, 12), 256>>>(rot, trans);
  k_r2d<<<1024, 384>>>(x2d);
  k_outgemm<<<dim3(16, 3), 256>>>(Wout, bout, out);
}

// round 3
// speedup vs baseline: 1.0748x; 1.0748x over previous
#include <cuda_runtime.h>
#include <math.h>

#define LL1 1024
#define CC 384
#define HH 12
#define PP 128

#define SCALAR_W 0.14433756729740643f
#define POINT_WC 0.13608276348795434f
#define PAIR_W   0.5773502691896258f

#define PROJ 1152
#define FEAT 2112

// ------------- static scratch (no runtime allocation) -------------
__device__ float g_proj[LL1 * PROJ];
__device__ float g_q   [LL1 * 192];       // [i][h*16+s] (scaled)
__device__ float g_kT  [HH * 16 * LL1];   // [(h*16+s)][j]
__device__ float g_vT  [HH * 16 * LL1];   // [(h*16+c)][j]
__device__ float g_qp  [LL1 * 144];       // [i][h*12 + n*3+r] global frame
__device__ float g_kpT [HH * 12 * LL1];   // [(h*12+nr)][j]
__device__ float g_vpT [HH * 24 * LL1];   // [(h*24+nr)][j]
__device__ float g_sqq [HH * LL1];
__device__ float g_sqk [HH * LL1];
__device__ float g_Z   [(size_t)HH * LL1 * LL1];   // qk logits -> attn (in place)
__device__ float g_feat[(size_t)LL1 * FEAT];

// ------------- K1: projection GEMM X[1024x384] @ W[384x1152] -------------
__device__ __forceinline__ float wload(int r, int gc, const float* Wq,
    const float* Wkv, const float* Wqp, const float* Wkvp) {
  if (gc < 192) return Wq[r * 192 + gc];
  if (gc < 576) return Wkv[r * 384 + (gc - 192)];
  if (gc < 720) return Wqp[r * 144 + (gc - 576)];
  return Wkvp[r * 432 + (gc - 720)];
}

__global__ void k_projgemm(const float* __restrict__ x1d, const float* __restrict__ Wq,
                           const float* __restrict__ Wkv, const float* __restrict__ Wqp,
                           const float* __restrict__ Wkvp) {
  __shared__ float s_x[16][68];
  __shared__ float s_w[16][128];
  int tid = threadIdx.x;
  int tx = tid & 15, ty = tid >> 4;
  int i0 = blockIdx.x * 64, c0 = blockIdx.y * 128;
  float acc[4][8] = {};
  for (int k0 = 0; k0 < CC; k0 += 16) {
    __syncthreads();
    for (int idx = tid; idx < 1024; idx += 256) {
      int il = idx >> 4, kk = idx & 15;
      s_x[kk][il] = x1d[(i0 + il) * CC + k0 + kk];
    }
    for (int idx = tid; idx < 2048; idx += 256) {
      int kk = idx >> 7, cl = idx & 127;
      s_w[kk][cl] = wload(k0 + kk, c0 + cl, Wq, Wkv, Wqp, Wkvp);
    }
    __syncthreads();
#pragma unroll
    for (int kk = 0; kk < 16; kk++) {
      float xv[4], wv[8];
#pragma unroll
      for (int r = 0; r < 4; r++) xv[r] = s_x[kk][ty * 4 + r];
#pragma unroll
      for (int c = 0; c < 8; c++) wv[c] = s_w[kk][tx * 8 + c];
#pragma unroll
      for (int r = 0; r < 4; r++)
#pragma unroll
        for (int c = 0; c < 8; c++) acc[r][c] += xv[r] * wv[c];
    }
  }
#pragma unroll
  for (int r = 0; r < 4; r++)
#pragma unroll
    for (int c = 0; c < 8; c++)
      g_proj[(size_t)(i0 + ty * 4 + r) * PROJ + c0 + tx * 8 + c] = acc[r][c];
}

// ------------- K2: bias/split/rigid/norms per residue -------------
__global__ void k_post(const float* __restrict__ rot, const float* __restrict__ trans,
                       const float* __restrict__ bq, const float* __restrict__ bkv,
                       const float* __restrict__ bqp, const float* __restrict__ bkvp) {
  int i = blockIdx.x, tid = threadIdx.x;
  __shared__ float s_R[9], s_t[3], s_pt[96][3];
  if (tid < 9) s_R[tid] = rot[i * 9 + tid];
  else if (tid < 12) s_t[tid - 9] = trans[i * 3 + tid - 9];
  __syncthreads();
  const float* pr = &g_proj[(size_t)i * PROJ];
  for (int idx = tid; idx < 576; idx += 256) {
    if (idx < 192) {
      g_q[(size_t)i * 192 + idx] = (pr[idx] + bq[idx]) * SCALAR_W;
    } else {
      int m = idx - 192, hh = m >> 5, t = m & 31;
      float v = pr[idx] + bkv[m];
      if (t < 16) g_kT[(hh * 16 + t) * LL1 + i] = v;
      else        g_vT[(hh * 16 + t - 16) * LL1 + i] = v;
    }
  }
  for (int m = tid; m < 192; m += 256) {
    float p0, p1, p2;
    if (m < 48) {
      p0 = pr[576 + m] + bqp[m];
      p1 = pr[624 + m] + bqp[48 + m];
      p2 = pr[672 + m] + bqp[96 + m];
    } else {
      int mm = m - 48;
      p0 = pr[720 + mm] + bkvp[mm];
      p1 = pr[864 + mm] + bkvp[144 + mm];
      p2 = pr[1008 + mm] + bkvp[288 + mm];
    }
    float gx = s_R[0] * p0 + s_R[1] * p1 + s_R[2] * p2 + s_t[0];
    float gy = s_R[3] * p0 + s_R[4] * p1 + s_R[5] * p2 + s_t[1];
    float gz = s_R[6] * p0 + s_R[7] * p1 + s_R[8] * p2 + s_t[2];
    if (m < 48) {
      int hh = m >> 2, n = m & 3;
      size_t b = (size_t)i * 144 + hh * 12 + n * 3;
      g_qp[b] = gx; g_qp[b + 1] = gy; g_qp[b + 2] = gz;
      s_pt[m][0] = gx; s_pt[m][1] = gy; s_pt[m][2] = gz;
    } else {
      int mm = m - 48, hh = mm / 12, t = mm % 12;
      if (t < 4) {
        int b = (hh * 12 + t * 3) * LL1 + i;
        g_kpT[b] = gx; g_kpT[b + LL1] = gy; g_kpT[b + 2 * LL1] = gz;
        int sp = 48 + hh * 4 + t;
        s_pt[sp][0] = gx; s_pt[sp][1] = gy; s_pt[sp][2] = gz;
      } else {
        int b = (hh * 24 + (t - 4) * 3) * LL1 + i;
        g_vpT[b] = gx; g_vpT[b + LL1] = gy; g_vpT[b + 2 * LL1] = gz;
      }
    }
  }
  __syncthreads();
  if (tid < 24) {
    int hh = tid % 12; bool isq = tid < 12;
    float s = 0.f;
#pragma unroll
    for (int n = 0; n < 4; n++) {
      const float* p = s_pt[(isq ? 0 : 48) + hh * 4 + n];
      s += p[0] * p[0] + p[1] * p[1] + p[2] * p[2];
    }
    if (isq) g_sqq[hh * LL1 + i] = s;
    else     g_sqk[hh * LL1 + i] = s;
  }
}

// ------------- K3: qk + dist logits -> g_Z (no pair, no softmax) -------------
__global__ void k_qk(const float* __restrict__ tpw) {
  int i0 = blockIdx.x * 8, h = blockIdx.y, tid = threadIdx.x; // 256 threads
  __shared__ float s_q[8][16], s_qp[8][12], s_sqq[8];
  __shared__ float s_pw;
  if (tid < 128) s_q[tid >> 4][tid & 15] = g_q[(size_t)(i0 + (tid >> 4)) * 192 + h * 16 + (tid & 15)];
  else if (tid < 224) { int m = tid - 128; s_qp[m / 12][m % 12] = g_qp[(size_t)(i0 + m / 12) * 144 + h * 12 + m % 12]; }
  else if (tid < 232) s_sqq[tid - 224] = g_sqq[h * LL1 + i0 + tid - 224];
  else if (tid == 232) {
    float x = tpw[h];
    s_pw = -0.5f * POINT_WC * (fmaxf(x, 0.f) + log1pf(expf(-fabsf(x))));
  }
  __syncthreads();
  float pw = s_pw;
  for (int j = tid; j < 1024; j += 256) {
    float kv[16], kp[12];
#pragma unroll
    for (int s = 0; s < 16; s++) kv[s] = g_kT[(h * 16 + s) * LL1 + j];
#pragma unroll
    for (int r = 0; r < 12; r++) kp[r] = g_kpT[(h * 12 + r) * LL1 + j];
    float sqk = g_sqk[h * LL1 + j];
#pragma unroll
    for (int ii = 0; ii < 8; ii++) {
      float d = 0.f, pq = 0.f;
#pragma unroll
      for (int s = 0; s < 16; s++) d += s_q[ii][s] * kv[s];
#pragma unroll
      for (int r = 0; r < 12; r++) pq += s_qp[ii][r] * kp[r];
      g_Z[(size_t)(h * LL1 + i0 + ii) * LL1 + j] = d + pw * (s_sqq[ii] + sqk - 2.f * pq);
    }
  }
}

// ------------- K4: fused pair-bias + softmax + r_2d, block = one i -------------
// dynamic smem layout (floats):
//   s_attn [1024][12]  : 12288
//   s_A    [8][1024]   : 8192 (pair staging; reused as reduction buffer in phase C)
//   s_W    [128][12]   : 1536
//   s_b    [12], s_red [16*12]
#define FUSE_SMEM_BYTES 118784

__global__ __launch_bounds__(512) void k_fuse(const float* __restrict__ x2d,
                                              const float* __restrict__ Wp,
                                              const float* __restrict__ bp) {
  extern __shared__ float sm[];
  float* s_attn = sm;                 // 12288
  float* s_A    = sm + 12288;         // 8192
  float* s_W    = sm + 20480;         // 1536
  float* s_b    = sm + 22016;         // 12
  float* s_red  = sm + 22028;         // 192

  int i = blockIdx.x, tid = threadIdx.x;
  int lane = tid & 31, w = tid >> 5;
  for (int t = tid; t < 1536; t += 512) s_W[t] = Wp[t];
  if (tid < 12) s_b[tid] = bp[tid];

  const float* xrow = x2d + (size_t)i * LL1 * PP;

  // ---- phase A: pair GEMM (1024 j x 128 c -> 12 h) ----
  float accp[2][12] = {};
  for (int k0 = 0; k0 < 128; k0 += 8) {
    __syncthreads();
#pragma unroll
    for (int p = 0; p < 4; p++) {
      int idx = p * 512 + tid;
      int r = idx >> 1, qq = idx & 1;
      float4 v = *(const float4*)(xrow + (size_t)r * PP + k0 + qq * 4);
      s_A[(qq * 4 + 0) * 1024 + r] = v.x;
      s_A[(qq * 4 + 1) * 1024 + r] = v.y;
      s_A[(qq * 4 + 2) * 1024 + r] = v.z;
      s_A[(qq * 4 + 3) * 1024 + r] = v.w;
    }
    __syncthreads();
#pragma unroll
    for (int kk = 0; kk < 8; kk++) {
      float a0 = s_A[kk * 1024 + tid];
      float a1 = s_A[kk * 1024 + tid + 512];
      float4 w0 = *(const float4*)&s_W[(k0 + kk) * 12];
      float4 w1 = *(const float4*)&s_W[(k0 + kk) * 12 + 4];
      float4 w2 = *(const float4*)&s_W[(k0 + kk) * 12 + 8];
      accp[0][0] += a0 * w0.x; accp[0][1] += a0 * w0.y; accp[0][2] += a0 * w0.z; accp[0][3] += a0 * w0.w;
      accp[0][4] += a0 * w1.x; accp[0][5] += a0 * w1.y; accp[0][6] += a0 * w1.z; accp[0][7] += a0 * w1.w;
      accp[0][8] += a0 * w2.x; accp[0][9] += a0 * w2.y; accp[0][10] += a0 * w2.z; accp[0][11] += a0 * w2.w;
      accp[1][0] += a1 * w0.x; accp[1][1] += a1 * w0.y; accp[1][2] += a1 * w0.z; accp[1][3] += a1 * w0.w;
      accp[1][4] += a1 * w1.x; accp[1][5] += a1 * w1.y; accp[1][6] += a1 * w1.z; accp[1][7] += a1 * w1.w;
      accp[1][8] += a1 * w2.x; accp[1][9] += a1 * w2.y; accp[1][10] += a1 * w2.z; accp[1][11] += a1 * w2.w;
    }
  }
  __syncthreads();
  // combine pair bias with qk logits from g_Z into s_attn[j][h]
#pragma unroll
  for (int q = 0; q < 2; q++) {
    int j = q * 512 + tid;
#pragma unroll
    for (int h = 0; h < 12; h++)
      s_attn[j * 12 + h] = PAIR_W * (accp[q][h] + s_b[h]) + g_Z[(size_t)(h * LL1 + i) * LL1 + j];
  }
  __syncthreads();

  // ---- phase B: softmax over j for all 12 h ----
  float mx[12];
#pragma unroll
  for (int h = 0; h < 12; h++)
    mx[h] = fmaxf(s_attn[tid * 12 + h], s_attn[(tid + 512) * 12 + h]);
#pragma unroll
  for (int h = 0; h < 12; h++)
#pragma unroll
    for (int o = 16; o; o >>= 1) mx[h] = fmaxf(mx[h], __shfl_xor_sync(~0u, mx[h], o));
  if (lane == 0) {
#pragma unroll
    for (int h = 0; h < 12; h++) s_red[w * 12 + h] = mx[h];
  }
  __syncthreads();
  if (tid < 12) {
    float m = s_red[tid];
#pragma unroll
    for (int ww = 1; ww < 16; ww++) m = fmaxf(m, s_red[ww * 12 + tid]);
    s_red[tid] = m;
  }
  __syncthreads();
  float bm[12];
#pragma unroll
  for (int h = 0; h < 12; h++) bm[h] = s_red[h];
  __syncthreads();

  float sum_[12];
#pragma unroll
  for (int h = 0; h < 12; h++) sum_[h] = 0.f;
#pragma unroll
  for (int q = 0; q < 2; q++) {
    int j = q * 512 + tid;
#pragma unroll
    for (int h = 0; h < 12; h++) {
      float e = __expf(s_attn[j * 12 + h] - bm[h]);
      s_attn[j * 12 + h] = e;
      sum_[h] += e;
    }
  }
#pragma unroll
  for (int h = 0; h < 12; h++)
#pragma unroll
    for (int o = 16; o; o >>= 1) sum_[h] += __shfl_xor_sync(~0u, sum_[h], o);
  if (lane == 0) {
#pragma unroll
    for (int h = 0; h < 12; h++) s_red[w * 12 + h] = sum_[h];
  }
  __syncthreads();
  if (tid < 12) {
    float s = 0.f;
#pragma unroll
    for (int ww = 0; ww < 16; ww++) s += s_red[ww * 12 + tid];
    s_red[tid] = 1.f / s;
  }
  __syncthreads();
  float inv[12];
#pragma unroll
  for (int h = 0; h < 12; h++) inv[h] = s_red[h];
  // normalize; write attn to g_Z (coalesced per h) and keep in smem
#pragma unroll
  for (int q = 0; q < 2; q++) {
    int j = q * 512 + tid;
#pragma unroll
    for (int h = 0; h < 12; h++) {
      float a = s_attn[j * 12 + h] * inv[h];
      s_attn[j * 12 + h] = a;
      g_Z[(size_t)(h * LL1 + i) * LL1 + j] = a;
    }
  }
  __syncthreads();

  // ---- phase C: r_2d = attn @ x2d (x2d re-read hits L2) ----
  int c = tid & 127, gsec = tid >> 7;  // 4 j-sections of 256
  float acc[12];
#pragma unroll
  for (int h = 0; h < 12; h++) acc[h] = 0.f;
  const float* xr = xrow + (size_t)(gsec * 256) * PP + c;
#pragma unroll 4
  for (int jj = 0; jj < 256; jj++) {
    float xv = xr[(size_t)jj * PP];
    const float* ap = &s_attn[(gsec * 256 + jj) * 12];
    float4 a0 = *(const float4*)ap;
    float4 a1 = *(const float4*)(ap + 4);
    float4 a2 = *(const float4*)(ap + 8);
    acc[0] += a0.x * xv; acc[1] += a0.y * xv; acc[2] += a0.z * xv; acc[3] += a0.w * xv;
    acc[4] += a1.x * xv; acc[5] += a1.y * xv; acc[6] += a1.z * xv; acc[7] += a1.w * xv;
    acc[8] += a2.x * xv; acc[9] += a2.y * xv; acc[10] += a2.z * xv; acc[11] += a2.w * xv;
  }
  __syncthreads();
#pragma unroll
  for (int h = 0; h < 12; h++) s_A[(gsec * 128 + c) * 12 + h] = acc[h];
  __syncthreads();
  if (tid < 128) {
#pragma unroll
    for (int h = 0; h < 12; h++) {
      float s = s_A[tid * 12 + h] + s_A[(128 + tid) * 12 + h] +
                s_A[(256 + tid) * 12 + h] + s_A[(384 + tid) * 12 + h];
      g_feat[(size_t)i * FEAT + 576 + h * PP + tid] = s;
    }
  }
}

// ------------- K5: attn @ {v_s, vp} + inverse rigid + f_n -------------
__global__ void k_attnout(const float* __restrict__ rot, const float* __restrict__ trans) {
  int i0 = blockIdx.x * 8, h = blockIdx.y;
  int tid = threadIdx.x, lane = tid & 31, w = tid >> 5;
  __shared__ float s_out[40][8];
  float acc[5][8];
#pragma unroll
  for (int c = 0; c < 5; c++)
#pragma unroll
    for (int ii = 0; ii < 8; ii++) acc[c][ii] = 0.f;
  const float* vptr[5];
#pragma unroll
  for (int c = 0; c < 5; c++) {
    int ch = w * 5 + c;
    vptr[c] = (ch < 16) ? &g_vT[(h * 16 + ch) * LL1] : &g_vpT[(h * 24 + ch - 16) * LL1];
  }
  for (int j = lane; j < 1024; j += 32) {
    float a[8];
#pragma unroll
    for (int ii = 0; ii < 8; ii++) a[ii] = g_Z[(size_t)(h * LL1 + i0 + ii) * LL1 + j];
#pragma unroll
    for (int c = 0; c < 5; c++) {
      float v = vptr[c][j];
#pragma unroll
      for (int ii = 0; ii < 8; ii++) acc[c][ii] += a[ii] * v;
    }
  }
#pragma unroll
  for (int c = 0; c < 5; c++)
#pragma unroll
    for (int ii = 0; ii < 8; ii++) {
      float s = acc[c][ii];
      for (int o = 16; o; o >>= 1) s += __shfl_xor_sync(~0u, s, o);
      if (lane == 0) s_out[w * 5 + c][ii] = s;
    }
  __syncthreads();
  if (tid < 128) {
    int ii = tid >> 4, c = tid & 15;
    g_feat[(size_t)(i0 + ii) * FEAT + h * 16 + c] = s_out[c][ii];
  } else if (tid < 192) {
    int p = tid - 128, ii = p >> 3, n = p & 7;
    int gi = i0 + ii;
    float R[9], t[3];
#pragma unroll
    for (int q = 0; q < 9; q++) R[q] = rot[gi * 9 + q];
#pragma unroll
    for (int q = 0; q < 3; q++) t[q] = trans[gi * 3 + q];
    float d0 = s_out[16 + n * 3 + 0][ii] - t[0];
    float d1 = s_out[16 + n * 3 + 1][ii] - t[1];
    float d2 = s_out[16 + n * 3 + 2][ii] - t[2];
    float lx = R[0] * d0 + R[3] * d1 + R[6] * d2;
    float ly = R[1] * d0 + R[4] * d1 + R[7] * d2;
    float lz = R[2] * d0 + R[5] * d1 + R[8] * d2;
    size_t base = (size_t)gi * FEAT;
    g_feat[base + 192 + 0 * 96 + h * 8 + n] = lx;
    g_feat[base + 192 + 1 * 96 + h * 8 + n] = ly;
    g_feat[base + 192 + 2 * 96 + h * 8 + n] = lz;
    g_feat[base + 480 + h * 8 + n] = sqrtf(lx * lx + ly * ly + lz * lz + 1e-8f);
  }
}

// ------------- K7: output GEMM feat[1024x2112] @ Wout[2112x384] -------------
__global__ void k_outgemm(const float* __restrict__ Wout, const float* __restrict__ bout,
                          float* __restrict__ out) {
  __shared__ float s_f[16][68];
  __shared__ float s_w[16][68];
  int tid = threadIdx.x;
  int tx = tid & 15, ty = tid >> 4;
  int i0 = blockIdx.x * 64, c0 = blockIdx.y * 64;
  float acc[4][4] = {};
  for (int k0 = 0; k0 < FEAT; k0 += 16) {
    __syncthreads();
    for (int idx = tid; idx < 1024; idx += 256) {
      int il = idx >> 4, kk = idx & 15;
      s_f[kk][il] = g_feat[(size_t)(i0 + il) * FEAT + k0 + kk];
    }
    for (int idx = tid; idx < 1024; idx += 256) {
      int kk = idx >> 6, cl = idx & 63;
      s_w[kk][cl] = Wout[(size_t)(k0 + kk) * 384 + c0 + cl];
    }
    __syncthreads();
#pragma unroll
    for (int kk = 0; kk < 16; kk++) {
      float xv[4], wv[4];
#pragma unroll
      for (int r = 0; r < 4; r++) xv[r] = s_f[kk][ty * 4 + r];
#pragma unroll
      for (int cc = 0; cc < 4; cc++) wv[cc] = s_w[kk][tx * 4 + cc];
#pragma unroll
      for (int r = 0; r < 4; r++)
#pragma unroll
        for (int cc = 0; cc < 4; cc++) acc[r][cc] += xv[r] * wv[cc];
    }
  }
#pragma unroll
  for (int r = 0; r < 4; r++) {
    int ii = i0 + ty * 4 + r;
#pragma unroll
    for (int cc = 0; cc < 4; cc++) {
      int ccol = c0 + tx * 4 + cc;
      out[(size_t)ii * 384 + ccol] = acc[r][cc] + bout[ccol];
    }
  }
}

// ------------- launch -------------
extern "C" void kernel_launch(void* const* d_in, const int* in_sizes, int n_in,
                              void* d_out, int out_size) {
  (void)in_sizes; (void)n_in; (void)out_size;
  const float* x1d   = (const float*)d_in[0];
  const float* x2d   = (const float*)d_in[1];
  const float* rot   = (const float*)d_in[2];
  const float* trans = (const float*)d_in[3];
  // d_in[4] = mask (all true) — unused
  const float* Wq    = (const float*)d_in[5];
  const float* bq    = (const float*)d_in[6];
  const float* Wkv   = (const float*)d_in[7];
  const float* bkv   = (const float*)d_in[8];
  const float* Wqp   = (const float*)d_in[9];
  const float* bqp   = (const float*)d_in[10];
  const float* Wkvp  = (const float*)d_in[11];
  const float* bkvp  = (const float*)d_in[12];
  const float* Wpair = (const float*)d_in[13];
  const float* bpair = (const float*)d_in[14];
  const float* tpw   = (const float*)d_in[15];
  const float* Wout  = (const float*)d_in[16];
  const float* bout  = (const float*)d_in[17];
  float* out = (float*)d_out;

  cudaFuncSetAttribute(k_fuse, cudaFuncAttributeMaxDynamicSharedMemorySize, FUSE_SMEM_BYTES);

  k_projgemm<<<dim3(16, 9), 256>>>(x1d, Wq, Wkv, Wqp, Wkvp);
  k_post<<<1024, 256>>>(rot, trans, bq, bkv, bqp, bkvp);
  k_qk<<<dim3(128, 12), 256>>>(tpw);
  k_fuse<<<1024, 512, FUSE_SMEM_BYTES>>>(x2d, Wpair, bpair);
  k_attnout<<<dim3(128, 12), 256>>>(rot, trans);
  k_outgemm<<<dim3(16, 6), 256>>>(Wout, bout, out);
}